// round 6
// baseline (speedup 1.0000x reference)
#include <cuda_runtime.h>
#include <math.h>
#include <stdint.h>

#define B_     128
#define HID_   512
#define NG_    2048
#define VOCAB_ 1000
#define VTOT_  3048
#define ROWS_  3072
#define T_     256
#define GRID_  148
#define NTHR   256
#define XCTAS  128           // 32 M-tiles (96 rows) x 4 K-splits

#define OUT_H  (B_*T_*VOCAB_)
#define OUT_C  (OUT_H + B_*HID_)

// ---------------- device scratch ----------------
__device__ __align__(16) float g_E2[VOCAB_*NG_];     // [v][u][4]: i,f,g,o
__device__ __align__(16) float g_base[NG_*B_];       // col-major [gatecol][r]
__device__ __align__(16) float g_Gred[NG_*B_];       // reduced gates (base+4 partials)
__device__ __align__(16) float g_hhi[B_*HID_];       // tf32-hi of h
__device__ __align__(16) float g_hlo[B_*HID_];       // tf32-lo of h
__device__ __align__(16) float g_part[4*ROWS_*B_];   // [k][row][r]
__device__ unsigned long long g_pack[2][B_];
__device__ unsigned g_bar;

__device__ __forceinline__ float tf32_rd(float x){
  uint32_t u; asm("cvt.rna.tf32.f32 %0, %1;" : "=r"(u) : "f"(x));
  return __uint_as_float(u);
}
__device__ __forceinline__ unsigned fkey(float x){
  unsigned u = __float_as_uint(x);
  return (u & 0x80000000u) ? ~u : (u | 0x80000000u);
}
__device__ __forceinline__ void mma_tf32(float* d, const uint32_t* a, const uint32_t* b){
  asm volatile("mma.sync.aligned.m16n8k8.row.col.f32.tf32.tf32.f32 "
    "{%0,%1,%2,%3}, {%4,%5,%6,%7}, {%8,%9}, {%0,%1,%2,%3};"
    : "+f"(d[0]), "+f"(d[1]), "+f"(d[2]), "+f"(d[3])
    : "r"(a[0]), "r"(a[1]), "r"(a[2]), "r"(a[3]), "r"(b[0]), "r"(b[1]));
}
__device__ __forceinline__ void cp16(float* smem_dst, const float* gsrc){
  uint32_t s = (uint32_t)__cvta_generic_to_shared(smem_dst);
  asm volatile("cp.async.cg.shared.global [%0], [%1], 16;" :: "r"(s), "l"(gsrc));
}
#define CP_COMMIT  asm volatile("cp.async.commit_group;" ::: "memory")
#define CP_WAIT(n) asm volatile("cp.async.wait_group %0;" :: "n"(n) : "memory")
#define DOT4(acc, a, b) acc = fmaf((a).x,(b).x, fmaf((a).y,(b).y, fmaf((a).z,(b).z, fmaf((a).w,(b).w,(acc)))))

// ---------------- prologue 1: E2 = embed @ Wih_emb^T ----------------
__global__ void __launch_bounds__(256) k_E(const float* __restrict__ emb,
                                           const float* __restrict__ Wih){
  __shared__ float As[16*68], Bs[16*68];
  const int tid = threadIdx.x;
  const int tx = tid & 15, ty = tid >> 4;
  const int c0 = blockIdx.x * 64, v0 = blockIdx.y * 64;
  float acc[4][4];
#pragma unroll
  for (int i=0;i<4;++i)
#pragma unroll
    for (int j=0;j<4;++j) acc[i][j] = 0.f;

  const int rr = tid >> 2, kq = tid & 3;
  for (int kc = 0; kc < 512; kc += 16){
    int v = v0 + rr; if (v >= VOCAB_) v = VOCAB_ - 1;
    float4 a = __ldg((const float4*)(emb + (size_t)v*512 + kc + 4*kq));
    As[(4*kq+0)*68 + rr] = a.x; As[(4*kq+1)*68 + rr] = a.y;
    As[(4*kq+2)*68 + rr] = a.z; As[(4*kq+3)*68 + rr] = a.w;
    int g = c0 + rr;
    float4 b = __ldg((const float4*)(Wih + (size_t)g*1024 + 512 + kc + 4*kq));
    Bs[(4*kq+0)*68 + rr] = b.x; Bs[(4*kq+1)*68 + rr] = b.y;
    Bs[(4*kq+2)*68 + rr] = b.z; Bs[(4*kq+3)*68 + rr] = b.w;
    __syncthreads();
#pragma unroll
    for (int k = 0; k < 16; ++k){
      float4 av = *(const float4*)&As[k*68 + ty*4];
      float4 bv = *(const float4*)&Bs[k*68 + tx*4];
      float ai[4] = {av.x, av.y, av.z, av.w};
      float bj[4] = {bv.x, bv.y, bv.z, bv.w};
#pragma unroll
      for (int i=0;i<4;++i)
#pragma unroll
        for (int j=0;j<4;++j) acc[i][j] = fmaf(ai[i], bj[j], acc[i][j]);
    }
    __syncthreads();
  }
  for (int i=0;i<4;++i){
    int v = v0 + ty*4 + i;
    if (v < VOCAB_)
      for (int j=0;j<4;++j){
        int c = c0 + tx*4 + j;
        g_E2[((size_t)v*512 + (c & 511))*4 + (c >> 9)] = acc[i][j];
      }
  }
}

// ---------------- prologue 2: g_base (exact fp32) ----------------
__global__ void __launch_bounds__(256) k_base(const float* __restrict__ Wih,
                                              const float* __restrict__ bih,
                                              const float* __restrict__ bhh,
                                              const float* __restrict__ ctx){
  __shared__ float xs[128*68], wsm[16*68];
  const int tid = threadIdx.x, blk = blockIdx.x;
  const int tx = tid & 7, ty = tid >> 3, r0 = ty*4;
  const int gc0 = blk*16 + 2*tx, gc1 = gc0 + 1;
  float acc[4][2];
#pragma unroll
  for (int i=0;i<4;++i){ acc[i][0]=0.f; acc[i][1]=0.f; }

  for (int kc = 0; kc < 512; kc += 64){
    for (int p = 0; p < 8; ++p){
      int lin = tid + p*256; int r = lin >> 4, kq2 = lin & 15;
      *(float4*)&xs[r*68 + 4*kq2] = __ldg((const float4*)(ctx + (size_t)r*512 + kc + 4*kq2));
    }
    { int cc = tid >> 4, kq2 = tid & 15;
      *(float4*)&wsm[cc*68 + 4*kq2] =
        __ldg((const float4*)(Wih + (size_t)(blk*16+cc)*1024 + kc + 4*kq2)); }
    __syncthreads();
#pragma unroll
    for (int k4 = 0; k4 < 16; ++k4){
      int kl = 4*k4;
      float4 w0 = *(const float4*)&wsm[(2*tx)*68 + kl];
      float4 w1 = *(const float4*)&wsm[(2*tx+1)*68 + kl];
#pragma unroll
      for (int i=0;i<4;++i){
        float4 h4 = *(const float4*)&xs[(r0+i)*68 + kl];
        DOT4(acc[i][0], h4, w0); DOT4(acc[i][1], h4, w1);
      }
    }
    __syncthreads();
  }
  float bb0 = __ldg(bih+gc0) + __ldg(bhh+gc0);
  float bb1 = __ldg(bih+gc1) + __ldg(bhh+gc1);
  for (int i=0;i<4;++i){
    g_base[(size_t)gc0*B_ + r0+i] = acc[i][0] + bb0;
    g_base[(size_t)gc1*B_ + r0+i] = acc[i][1] + bb1;
  }
}

// ---------------- prologue 3 ----------------
__global__ void k_init(const float* __restrict__ ctx, const int* __restrict__ sid){
  int idx = blockIdx.x*blockDim.x + threadIdx.x;
  if (idx < B_*HID_){
    float x = ctx[idx];
    float hi = tf32_rd(x);
    g_hhi[idx] = hi;
    g_hlo[idx] = tf32_rd(x - hi);
  }
  if (idx < B_){
    g_pack[0][idx] = (unsigned long long)(unsigned)((VOCAB_-1) - *sid);
    g_pack[1][idx] = 0ull;
  }
  if (idx == 0) g_bar = 0u;
}

// ---------------- grid barrier ----------------
__device__ __forceinline__ void gbar(unsigned target){
  __syncthreads();
  if (threadIdx.x == 0){
    __threadfence();
    atomicAdd(&g_bar, 1u);
    while (*(volatile unsigned*)&g_bar < target) { }
    __threadfence();
  }
  __syncthreads();
}

// ---------------- persistent kernel ----------------
// smem float offsets
#define SA_H    0                      // A hi frag-packed: 96*128 = 12288
#define SA_L    12288                  // A lo
#define SB_H(b) (24576 + (b)*9216)     // B hi tile [128][36]
#define SB_L(b) (24576 + (b)*9216 + 4608)
#define S_TOK   43008                  // 128 ints
#define S_LS    43136                  // 8*128 floats
#define SMW_    44160                  // 176640 bytes

__global__ void __launch_bounds__(NTHR, 1)
k_persist(const float* __restrict__ Whh, const float* __restrict__ Wout,
          const float* __restrict__ bout, float* __restrict__ out){
  extern __shared__ float sm[];
  float* Ah = sm + SA_H;
  float* Al = sm + SA_L;
  int*   toks = (int*)(sm + S_TOK);
  float* Ls = sm + S_LS;

  const int cta = blockIdx.x, tid = threadIdx.x;
  const int wid = tid >> 5, lane = tid & 31;
  const bool isX = (cta < XCTAS);
  const int mtile = cta >> 2, kidx = cta & 3, kbase = kidx*128;
  const int wm = wid >> 2, wn = wid & 3;          // warp tile 48M x 32N

  // ---- stage A (weights hi/lo, fragment-packed) once ----
  if (isX){
    for (int lin = tid; lin < 3072; lin += NTHR){
      int ml = lin >> 5, q = lin & 31;
      int gm = mtile*96 + ml;
      float4 w = make_float4(0.f,0.f,0.f,0.f);
      if (gm < NG_)        w = __ldg((const float4*)(Whh  + (size_t)gm*HID_ + kbase + q*4));
      else if (gm < VTOT_) w = __ldg((const float4*)(Wout + (size_t)(gm-NG_)*HID_ + kbase + q*4));
      int f = (ml >> 4)*16 + (q >> 1);
      int ofs = f*128 + (ml & 7)*16 + ((ml >> 3) & 1) + 2*(q & 1);
      float hi;
      hi = tf32_rd(w.x); Ah[ofs+ 0] = hi; Al[ofs+ 0] = tf32_rd(w.x - hi);
      hi = tf32_rd(w.y); Ah[ofs+ 4] = hi; Al[ofs+ 4] = tf32_rd(w.y - hi);
      hi = tf32_rd(w.z); Ah[ofs+ 8] = hi; Al[ofs+ 8] = tf32_rd(w.z - hi);
      hi = tf32_rd(w.w); Ah[ofs+12] = hi; Al[ofs+12] = tf32_rd(w.w - hi);
    }
  }
  __syncthreads();

  float cr0 = 0.f, cr1 = 0.f;
  const int yi0 = cta*NTHR + tid;
  const int yi1 = yi0 + GRID_*NTHR;

  unsigned bt = 0;
  for (int m = 0; m <= T_; ++m){
    // ================ phase X: 3xTF32 mma.sync, cp.async pipelined ====
    if (isX){
      float acc[12][4];
#pragma unroll
      for (int i=0;i<12;++i)
#pragma unroll
        for (int j=0;j<4;++j) acc[i][j] = 0.f;

      // prefetch chunk 0 (32 K-floats, hi+lo)
#pragma unroll
      for (int p = 0; p < 8; ++p){
        int lin = tid + p*NTHR;
        int r = lin >> 4, q = lin & 15;
        if (q < 8) cp16(sm + SB_H(0) + r*36 + q*4,
                        g_hhi + (size_t)r*HID_ + kbase + q*4);
        else       cp16(sm + SB_L(0) + r*36 + (q-8)*4,
                        g_hlo + (size_t)r*HID_ + kbase + (q-8)*4);
      }
      CP_COMMIT;

      for (int c = 0; c < 4; ++c){
        if (c < 3){
          const int nb = (c+1) & 1, ko = kbase + (c+1)*32;
#pragma unroll
          for (int p = 0; p < 8; ++p){
            int lin = tid + p*NTHR;
            int r = lin >> 4, q = lin & 15;
            if (q < 8) cp16(sm + SB_H(nb) + r*36 + q*4,
                            g_hhi + (size_t)r*HID_ + ko + q*4);
            else       cp16(sm + SB_L(nb) + r*36 + (q-8)*4,
                            g_hlo + (size_t)r*HID_ + ko + (q-8)*4);
          }
          CP_COMMIT;
          CP_WAIT(1);
        } else {
          CP_WAIT(0);
        }
        __syncthreads();
        const float* Bhp = sm + SB_H(c & 1);
        const float* Blp = sm + SB_L(c & 1);
#pragma unroll
        for (int ksl = 0; ksl < 4; ++ksl){
          uint32_t bh[4][2], bl[4][2];
          int kk = ksl*8 + (lane & 3);
#pragma unroll
          for (int ni = 0; ni < 4; ++ni){
            int n = wn*32 + ni*8 + (lane >> 2);
            bh[ni][0] = __float_as_uint(Bhp[n*36 + kk]);
            bh[ni][1] = __float_as_uint(Bhp[n*36 + kk + 4]);
            bl[ni][0] = __float_as_uint(Blp[n*36 + kk]);
            bl[ni][1] = __float_as_uint(Blp[n*36 + kk + 4]);
          }
#pragma unroll
          for (int mi = 0; mi < 3; ++mi){
            int f = (wm*3 + mi)*16 + c*4 + ksl;
            uint4 ahv = *(const uint4*)&Ah[(f*32 + lane)*4];
            uint4 alv = *(const uint4*)&Al[(f*32 + lane)*4];
            const uint32_t* ah = (const uint32_t*)&ahv;
            const uint32_t* al = (const uint32_t*)&alv;
#pragma unroll
            for (int ni = 0; ni < 4; ++ni){
              mma_tf32(acc[mi*4+ni], ah, bh[ni]);
              mma_tf32(acc[mi*4+ni], ah, bl[ni]);
              mma_tf32(acc[mi*4+ni], al, bh[ni]);
            }
          }
        }
        __syncthreads();
      }
      // store D partials
#pragma unroll
      for (int mi = 0; mi < 3; ++mi){
#pragma unroll
        for (int ni = 0; ni < 4; ++ni){
          int row0 = mtile*96 + wm*48 + mi*16 + (lane >> 2);
          int col = wn*32 + ni*8 + (lane & 3)*2;
          float* dst = g_part + ((size_t)kidx*ROWS_ + row0)*B_ + col;
          *(float2*)dst = make_float2(acc[mi*4+ni][0], acc[mi*4+ni][1]);
          *(float2*)(dst + 8*B_) = make_float2(acc[mi*4+ni][2], acc[mi*4+ni][3]);
        }
      }
    }
    bt += GRID_; gbar(bt);

    // ================ phase Yv: gate-reduce + vocab reduce + argmax ====
    if (m < T_){
      // gate K-reduce into g_Gred (coalesced over batch)
      for (int lin = tid; lin < 14*128; lin += NTHR){
        int cl = cta*14 + (lin >> 7);
        if (cl < NG_){
          int r = lin & 127;
          float s = g_base[(size_t)cl*B_ + r];
          s += __ldcg(&g_part[(size_t)cl*B_ + r]);
          s += __ldcg(&g_part[((size_t)ROWS_ + cl)*B_ + r]);
          s += __ldcg(&g_part[((size_t)2*ROWS_ + cl)*B_ + r]);
          s += __ldcg(&g_part[((size_t)3*ROWS_ + cl)*B_ + r]);
          g_Gred[(size_t)cl*B_ + r] = s;
        }
      }
    }
    if (m >= 1){
      const int v0 = cta*7;
      if (wid < 7){
        int v = v0 + wid;
        if (v < VOCAB_){
          float bo = __ldg(bout + v);
          const float* p = g_part + (size_t)(NG_ + v)*B_;
#pragma unroll
          for (int rq = 0; rq < 4; ++rq){
            int r = rq*32 + lane;
            float sum = bo + __ldcg(p + r)
                      + __ldcg(p + (size_t)ROWS_*B_ + r)
                      + __ldcg(p + (size_t)2*ROWS_*B_ + r)
                      + __ldcg(p + (size_t)3*ROWS_*B_ + r);
            Ls[wid*128 + r] = sum;
          }
        }
      }
      __syncthreads();
      for (int it = tid; it < 128*8; it += NTHR){
        int r = it >> 3, vl = it & 7;
        int v = v0 + vl;
        if (vl < 7 && v < VOCAB_)
          out[((size_t)r*T_ + (m-1))*VOCAB_ + v] = Ls[vl*128 + r];
      }
      if (m < T_ && tid < 128){
        int r = tid;
        unsigned long long best = 0ull;
        for (int vl = 0; vl < 7; ++vl){
          int v = v0 + vl;
          if (v < VOCAB_){
            unsigned long long pk = ((unsigned long long)fkey(Ls[vl*128 + r]) << 32)
                                  | (unsigned)(VOCAB_-1 - v);
            if (pk > best) best = pk;
          }
        }
        if (best) atomicMax(&g_pack[m & 1][r], best);
      }
      __syncthreads();
    }
    if (m == T_) break;
    bt += GRID_; gbar(bt);

    // ================ phase Yc: E-gather + LSTM cell ================
    {
      if (tid < B_){
        unsigned long long p = __ldcg(&g_pack[m & 1][tid]);
        toks[tid] = (VOCAB_-1) - (int)(unsigned)(p & 0xffffffffull);
      }
      __syncthreads();
#pragma unroll
      for (int q = 0; q < 2; ++q){
        int idx = q ? yi1 : yi0;
        if (idx < B_*HID_){
          int r = idx & 127, u = idx >> 7;
          int tok = toks[r];
          float4 ev = __ldg((const float4*)&g_E2[((size_t)tok*HID_ + u)*4]);
          float gi = __ldcg(&g_Gred[(size_t)u*B_ + r]) + ev.x;
          float gf = __ldcg(&g_Gred[(size_t)(512+u)*B_ + r]) + ev.y;
          float gg = __ldcg(&g_Gred[(size_t)(1024+u)*B_ + r]) + ev.z;
          float go = __ldcg(&g_Gred[(size_t)(1536+u)*B_ + r]) + ev.w;
          gi = 1.f/(1.f + expf(-gi));
          gf = 1.f/(1.f + expf(-gf));
          gg = tanhf(gg);
          go = 1.f/(1.f + expf(-go));
          float cold = q ? cr1 : cr0;
          float cn = fmaf(gf, cold, gi*gg);
          if (q) cr1 = cn; else cr0 = cn;
          float hn = go * tanhf(cn);
          float hi = tf32_rd(hn);
          g_hhi[(size_t)r*HID_ + u] = hi;
          g_hlo[(size_t)r*HID_ + u] = tf32_rd(hn - hi);
          if (m == T_-1){
            out[OUT_H + (size_t)r*HID_ + u] = hn;
            out[OUT_C + (size_t)r*HID_ + u] = cn;
          }
        }
      }
      if (yi0 < B_) g_pack[(m+1) & 1][yi0] = 0ull;
    }
    bt += GRID_; gbar(bt);
  }
}

// ---------------- launch ----------------
extern "C" void kernel_launch(void* const* d_in, const int* in_sizes, int n_in,
                              void* d_out, int out_size){
  const float* ctx  = (const float*)d_in[0];
  const float* emb  = (const float*)d_in[1];
  const float* Wih  = (const float*)d_in[2];
  const float* bih  = (const float*)d_in[3];
  const float* Whh  = (const float*)d_in[4];
  const float* bhh  = (const float*)d_in[5];
  const float* Wout = (const float*)d_in[6];
  const float* bout = (const float*)d_in[7];
  const int*   sid  = (const int*)d_in[8];
  float* out = (float*)d_out;

  cudaFuncSetAttribute(k_persist, cudaFuncAttributeMaxDynamicSharedMemorySize,
                       SMW_ * 4);

  dim3 gE(32, 16);
  k_E<<<gE, 256>>>(emb, Wih);
  k_base<<<128, 256>>>(Wih, bih, bhh, ctx);
  k_init<<<256, 256>>>(ctx, sid);
  k_persist<<<GRID_, NTHR, SMW_ * 4>>>(Whh, Wout, bout, out);
}